// round 13
// baseline (speedup 1.0000x reference)
#include <cuda_runtime.h>
#include <math.h>
#include <stdint.h>

#define N_NODES 12288
#define D_IN    512
#define HID     256
#define D_OUT   64
#define E_EDGES 393216

#define NBLK        96                       // N_NODES / 128
#define LOWER_BLKS  (NBLK * (NBLK - 1) / 2)  // 4560 early-exit blocks -> edge work
#define EDGE_WARPS  (LOWER_BLKS * 8)         // 36480 warps over 393216 edges

// ---------------- scratch (device globals: no runtime allocation) ----------
__device__ float  g_h0[(size_t)N_NODES * HID];
__device__ float  g_h1[(size_t)N_NODES * HID];
__device__ float  g_zn[(size_t)N_NODES * D_OUT];
__device__ double g_loss_sum;

// ---------------------------------------------------------------------------
// tf32 / cp.async / sigmoid / streaming-store helpers
// ---------------------------------------------------------------------------
__device__ __forceinline__ uint32_t f32_to_tf32(float x) {
    uint32_t r;
    asm("cvt.rna.tf32.f32 %0, %1;" : "=r"(r) : "f"(x));
    return r;
}

__device__ __forceinline__ void mma_tf32(float d[4],
                                         const uint32_t a[4],
                                         const uint32_t b[2]) {
    asm volatile(
        "mma.sync.aligned.m16n8k8.row.col.f32.tf32.tf32.f32 "
        "{%0,%1,%2,%3}, {%4,%5,%6,%7}, {%8,%9}, {%0,%1,%2,%3};"
        : "+f"(d[0]), "+f"(d[1]), "+f"(d[2]), "+f"(d[3])
        : "r"(a[0]), "r"(a[1]), "r"(a[2]), "r"(a[3]),
          "r"(b[0]), "r"(b[1]));
}

__device__ __forceinline__ void cp_async16(float* smem_dst, const float* gmem_src) {
    uint32_t s = (uint32_t)__cvta_generic_to_shared(smem_dst);
    asm volatile("cp.async.cg.shared.global [%0], [%1], 16;"
                 :: "r"(s), "l"(gmem_src));
}
#define CP_COMMIT()      asm volatile("cp.async.commit_group;")
#define CP_WAIT(n)       asm volatile("cp.async.wait_group %0;" :: "n"(n))

__device__ __forceinline__ float fast_sigmoid(float x) {
    float t;
    asm("tanh.approx.f32 %0, %1;" : "=f"(t) : "f"(x * 0.5f));
    return fmaf(t, 0.5f, 0.5f);
}

__device__ __forceinline__ void stg_cs_f2(float* p, float a, float b) {
    asm volatile("st.global.cs.v2.f32 [%0], {%1,%2};"
                 :: "l"(p), "f"(a), "f"(b) : "memory");
}
__device__ __forceinline__ void stg_cs_f1(float* p, float a) {
    asm volatile("st.global.cs.f32 [%0], %1;" :: "l"(p), "f"(a) : "memory");
}

// ---------------------------------------------------------------------------
// Encoder GEMM on tensor cores, cp.async double-buffered.
//   Layers 1,2: BM=64,  BN=128 (grid 2x192)  — best measured (R12)
//   Layer  3 : BM=128, BN=64  (grid 1x96)   — best measured (R11), fused norm
// ---------------------------------------------------------------------------
#define LDA 36

template<int BM, int BN, bool RELU, bool NORM>
__global__ __launch_bounds__(256)
void gemm_mma_kernel(const float* __restrict__ A,
                     const float* __restrict__ W,
                     const float* __restrict__ bias,
                     float* __restrict__ C,
                     int K, int Nn)
{
    constexpr int LDW = BN + 4;
    constexpr int WN  = BN / 32;
    constexpr int WM  = 8 / WN;
    constexpr int MT  = BM / (WM * 16);
    constexpr int NT  = 4;
    static_assert(MT >= 1, "bad BM/BN combo");

    constexpr int A_FLOATS = BM * LDA;
    constexpr int W_FLOATS = 32 * LDW;
    constexpr int NEED_MAIN = 2 * (A_FLOATS + W_FLOATS);
    constexpr int NEED_STG  = NORM ? BM * 68 : 0;
    constexpr int SMEM_FLOATS = NEED_MAIN > NEED_STG ? NEED_MAIN : NEED_STG;

    __shared__ float smem[SMEM_FLOATS];
    float* Asb[2] = { smem, smem + A_FLOATS + W_FLOATS };
    float* Wsb[2] = { smem + A_FLOATS, smem + 2*A_FLOATS + W_FLOATS };

    const int tid  = threadIdx.x;
    const int lane = tid & 31;
    const int wid  = tid >> 5;
    const int wm   = (wid / WN) * (MT * 16);
    const int wn   = (wid % WN) * 32;
    const int qr   = lane >> 2;
    const int qc   = lane & 3;
    const int rowBase = blockIdx.y * BM;
    const int colBase = blockIdx.x * BN;

    auto load_tiles = [&](int kk, int buf) {
        float* As = Asb[buf];
        float* Ws = Wsb[buf];
#pragma unroll
        for (int v = tid; v < BM * 8; v += 256) {
            const int r  = v >> 3;
            const int c4 = (v & 7) * 4;
            cp_async16(&As[r * LDA + c4],
                       &A[(size_t)(rowBase + r) * K + kk + c4]);
        }
#pragma unroll
        for (int v = tid; v < 32 * (BN/4); v += 256) {
            const int kr = v / (BN/4);
            const int n4 = (v % (BN/4)) * 4;
            cp_async16(&Ws[kr * LDW + n4],
                       &W[(size_t)(kk + kr) * Nn + colBase + n4]);
        }
        CP_COMMIT();
    };

    float acc[MT][NT][4];
#pragma unroll
    for (int mt = 0; mt < MT; mt++)
#pragma unroll
        for (int nt = 0; nt < NT; nt++)
#pragma unroll
            for (int i = 0; i < 4; i++) acc[mt][nt][i] = 0.f;

    load_tiles(0, 0);

    int buf = 0;
    for (int kk = 0; kk < K; kk += 32, buf ^= 1) {
        if (kk + 32 < K) {
            load_tiles(kk + 32, buf ^ 1);
            CP_WAIT(1);
        } else {
            CP_WAIT(0);
        }
        __syncthreads();

        const float* As = Asb[buf];
        const float* Ws = Wsb[buf];
#pragma unroll
        for (int k0 = 0; k0 < 32; k0 += 8) {
            uint32_t a[MT][4], b[NT][2];
#pragma unroll
            for (int mt = 0; mt < MT; mt++) {
                const float* base = &As[(wm + mt*16 + qr) * LDA + k0 + qc];
                a[mt][0] = f32_to_tf32(base[0]);
                a[mt][1] = f32_to_tf32(base[8 * LDA]);
                a[mt][2] = f32_to_tf32(base[4]);
                a[mt][3] = f32_to_tf32(base[8 * LDA + 4]);
            }
#pragma unroll
            for (int nt = 0; nt < NT; nt++) {
                const float* base = &Ws[(k0 + qc) * LDW + wn + nt*8 + qr];
                b[nt][0] = f32_to_tf32(base[0]);
                b[nt][1] = f32_to_tf32(base[4 * LDW]);
            }
#pragma unroll
            for (int mt = 0; mt < MT; mt++)
#pragma unroll
                for (int nt = 0; nt < NT; nt++)
                    mma_tf32(acc[mt][nt], a[mt], b[nt]);
        }
        __syncthreads();
    }

    if (!NORM) {
#pragma unroll
        for (int mt = 0; mt < MT; mt++) {
#pragma unroll
            for (int nt = 0; nt < NT; nt++) {
                float* d = acc[mt][nt];
                const int c = colBase + wn + nt*8 + qc*2;
                float bx = bias[c], by = bias[c+1];
                float2 lo = make_float2(d[0] + bx, d[1] + by);
                float2 hi = make_float2(d[2] + bx, d[3] + by);
                if (RELU) {
                    lo.x = fmaxf(lo.x, 0.f); lo.y = fmaxf(lo.y, 0.f);
                    hi.x = fmaxf(hi.x, 0.f); hi.y = fmaxf(hi.y, 0.f);
                }
                const size_t r0 = rowBase + wm + mt*16 + qr;
                *reinterpret_cast<float2*>(&C[r0 * Nn + c])     = lo;
                *reinterpret_cast<float2*>(&C[(r0+8) * Nn + c]) = hi;
            }
        }
    } else {
        constexpr int LDS = 68;
        float* stg = smem;                 // BM x 64, stride 68
        __syncthreads();
#pragma unroll
        for (int mt = 0; mt < MT; mt++) {
#pragma unroll
            for (int nt = 0; nt < NT; nt++) {
                float* d = acc[mt][nt];
                const int c = wn + nt*8 + qc*2;
                float bx = bias[c], by = bias[c+1];
                const int r = wm + mt*16 + qr;
                *reinterpret_cast<float2*>(&stg[r * LDS + c]) =
                    make_float2(d[0] + bx, d[1] + by);
                *reinterpret_cast<float2*>(&stg[(r+8) * LDS + c]) =
                    make_float2(d[2] + bx, d[3] + by);
            }
        }
        __syncthreads();
#pragma unroll
        for (int rr = 0; rr < BM/8; rr++) {
            const int r = wid * (BM/8) + rr;
            float2 v = *reinterpret_cast<const float2*>(&stg[r * LDS + lane*2]);
            float ss = v.x*v.x + v.y*v.y;
#pragma unroll
            for (int o = 16; o > 0; o >>= 1)
                ss += __shfl_xor_sync(0xffffffffu, ss, o);
            float inv = rsqrtf(fmaxf(ss, 1e-30f));
            *reinterpret_cast<float2*>(&C[(size_t)(rowBase + r) * D_OUT + lane*2]) =
                make_float2(v.x * inv, v.y * inv);
        }
    }
}

__global__ void zero_loss_kernel() { g_loss_sum = 0.0; }

__global__ void write_loss_kernel(float* __restrict__ out)
{
    out[(size_t)N_NODES * N_NODES] = (float)(g_loss_sum / (double)E_EDGES);
}

// ---------------------------------------------------------------------------
// Gram + sigmoid via tf32 mma (R11 structure) with the edge loss folded into
// the 4560 lower-triangle (bj<bi) blocks that previously early-exited:
// each gets a short contiguous slice of edges (~11 per warp), overlapping
// the write-bound gram wave. Upper blocks unchanged: cp.async staging,
// HW-tanh sigmoid, direct-register upper write + staged mirror, .cs stores.
// ---------------------------------------------------------------------------
#define GRAM_LDK  68
#define GRAM_LDS  132
#define GRAM_SMEM_BYTES (2 * 128 * GRAM_LDK * 4)   // 69,632 B (>= stage 67,584)

__global__ __launch_bounds__(256)
void gram_mma_kernel(const float* __restrict__ Z,
                     const int*   __restrict__ ei,
                     float* __restrict__ Out)
{
    const int bi = blockIdx.y;
    const int bj = blockIdx.x;
    const int tid  = threadIdx.x;
    const int lane = tid & 31;
    const int wid  = tid >> 5;

    // ---------- lower-triangle blocks: edge-loss slice, then exit ----------
    if (bj < bi) {
        const int id = (bi * (bi - 1)) / 2 + bj;     // 0 .. LOWER_BLKS-1
        const int gw = id * 8 + wid;                 // global warp id
        float lsum = 0.f;
        for (int e = gw; e < E_EDGES; e += EDGE_WARPS) {
            const int s = ei[e];
            const int d = ei[E_EDGES + e];
            float2 a = *reinterpret_cast<const float2*>(&Z[(size_t)s * D_OUT + lane*2]);
            float2 b = *reinterpret_cast<const float2*>(&Z[(size_t)d * D_OUT + lane*2]);
            float p = a.x*b.x + a.y*b.y;
#pragma unroll
            for (int o = 16; o > 0; o >>= 1)
                p += __shfl_xor_sync(0xffffffffu, p, o);
            if (lane == 0) lsum += log1pf(__expf(-p));
        }
        __shared__ float wsum[8];
        if (lane == 0) wsum[wid] = lsum;
        __syncthreads();
        if (tid == 0) {
            float t = 0.f;
#pragma unroll
            for (int i = 0; i < 8; i++) t += wsum[i];
            atomicAdd(&g_loss_sum, (double)t);
        }
        return;
    }

    // ---------- upper-triangle blocks: gram tile ----------
    const int rowBase = bi * 128;
    const int colBase = bj * 128;

    extern __shared__ float smem[];
    float* As = smem;                       // raw fp32
    float* Bs = smem + 128 * GRAM_LDK;

    const int wm = (wid >> 2) * 64;
    const int wn = (wid & 3) * 32;
    const int qr = lane >> 2;
    const int qc = lane & 3;

    for (int v = tid; v < 128 * 16; v += 256) {
        const int r  = v >> 4;
        const int c4 = (v & 15) * 4;
        cp_async16(&As[r * GRAM_LDK + c4],
                   &Z[(size_t)(rowBase + r) * D_OUT + c4]);
    }
    if (bj != bi) {
        for (int v = tid; v < 128 * 16; v += 256) {
            const int r  = v >> 4;
            const int c4 = (v & 15) * 4;
            cp_async16(&Bs[r * GRAM_LDK + c4],
                       &Z[(size_t)(colBase + r) * D_OUT + c4]);
        }
    }
    CP_COMMIT();
    CP_WAIT(0);
    __syncthreads();

    const float* Bp = (bj == bi) ? As : Bs;

    float acc[4][4][4];
#pragma unroll
    for (int mt = 0; mt < 4; mt++)
#pragma unroll
        for (int nt = 0; nt < 4; nt++)
#pragma unroll
            for (int i = 0; i < 4; i++) acc[mt][nt][i] = 0.f;

#pragma unroll
    for (int k0 = 0; k0 < D_OUT; k0 += 8) {
        uint32_t a[4][4], b[4][2];
#pragma unroll
        for (int mt = 0; mt < 4; mt++) {
            const float* base = &As[(wm + mt*16 + qr) * GRAM_LDK + k0 + qc];
            a[mt][0] = f32_to_tf32(base[0]);
            a[mt][1] = f32_to_tf32(base[8 * GRAM_LDK]);
            a[mt][2] = f32_to_tf32(base[4]);
            a[mt][3] = f32_to_tf32(base[8 * GRAM_LDK + 4]);
        }
#pragma unroll
        for (int nt = 0; nt < 4; nt++) {
            const float* base = &Bp[(wn + nt*8 + qr) * GRAM_LDK + k0 + qc];
            b[nt][0] = f32_to_tf32(base[0]);
            b[nt][1] = f32_to_tf32(base[4]);
        }
#pragma unroll
        for (int mt = 0; mt < 4; mt++)
#pragma unroll
            for (int nt = 0; nt < 4; nt++)
                mma_tf32(acc[mt][nt], a[mt], b[nt]);
    }

    // sigmoid (HW tanh) in registers, direct (upper) tile straight from regs
#pragma unroll
    for (int mt = 0; mt < 4; mt++) {
#pragma unroll
        for (int nt = 0; nt < 4; nt++) {
            float* d = acc[mt][nt];
            d[0] = fast_sigmoid(d[0]);
            d[1] = fast_sigmoid(d[1]);
            d[2] = fast_sigmoid(d[2]);
            d[3] = fast_sigmoid(d[3]);
            const size_t r = rowBase + wm + mt*16 + qr;
            const int    c = colBase + wn + nt*8 + qc*2;
            stg_cs_f2(&Out[r * N_NODES + c],     d[0], d[1]);
            stg_cs_f2(&Out[(r+8) * N_NODES + c], d[2], d[3]);
        }
    }

    // mirror (lower) tile: stage + transposed coalesced write
    if (bj > bi) {
        __syncthreads();
        float* stg = smem;                  // 128x128, stride 132
#pragma unroll
        for (int mt = 0; mt < 4; mt++) {
#pragma unroll
            for (int nt = 0; nt < 4; nt++) {
                float* d = acc[mt][nt];
                const int r = wm + mt*16 + qr;
                const int c = wn + nt*8 + qc*2;
                *reinterpret_cast<float2*>(&stg[r * GRAM_LDS + c]) =
                    make_float2(d[0], d[1]);
                *reinterpret_cast<float2*>(&stg[(r+8) * GRAM_LDS + c]) =
                    make_float2(d[2], d[3]);
            }
        }
        __syncthreads();
        for (int v = tid; v < 128 * 32; v += 256) {
            const int cc = v & 127;
            const int r2 = (v >> 7) * 4;
            float4 t = *reinterpret_cast<const float4*>(&stg[cc * GRAM_LDS + r2]);
            float* ob = &Out[(size_t)(colBase + r2) * N_NODES + rowBase + cc];
            stg_cs_f1(ob,             t.x);
            stg_cs_f1(ob + N_NODES,   t.y);
            stg_cs_f1(ob + 2*N_NODES, t.z);
            stg_cs_f1(ob + 3*N_NODES, t.w);
        }
    }
}

// ---------------------------------------------------------------------------
extern "C" void kernel_launch(void* const* d_in, const int* in_sizes, int n_in,
                              void* d_out, int out_size)
{
    const float* x  = (const float*)d_in[0];
    const int*   ei = (const int*)  d_in[1];
    const float* W0 = (const float*)d_in[2];
    const float* b0 = (const float*)d_in[3];
    const float* W1 = (const float*)d_in[4];
    const float* b1 = (const float*)d_in[5];
    const float* W2 = (const float*)d_in[6];
    const float* b2 = (const float*)d_in[7];
    float* out = (float*)d_out;

    void *p_h0, *p_h1, *p_zn;
    cudaGetSymbolAddress(&p_h0, g_h0);
    cudaGetSymbolAddress(&p_h1, g_h1);
    cudaGetSymbolAddress(&p_zn, g_zn);
    float* h0 = (float*)p_h0;
    float* h1 = (float*)p_h1;
    float* zn = (float*)p_zn;

    cudaFuncSetAttribute(gram_mma_kernel,
                         cudaFuncAttributeMaxDynamicSharedMemorySize,
                         GRAM_SMEM_BYTES);

    zero_loss_kernel<<<1, 1>>>();

    // encoder (tensor cores, cp.async double-buffered)
    gemm_mma_kernel<64,  128, true,  false><<<dim3(HID/128, N_NODES/64),  256>>>(
        x,  W0, b0, h0, D_IN, HID);
    gemm_mma_kernel<64,  128, true,  false><<<dim3(HID/128, N_NODES/64),  256>>>(
        h0, W1, b1, h1, HID,  HID);
    gemm_mma_kernel<128, 64,  false, true ><<<dim3(1,       N_NODES/128), 256>>>(
        h1, W2, b2, zn, HID,  D_OUT);

    // fused gram + edge loss: upper-tri blocks do gram tiles, lower-tri
    // blocks (previously early-exit) do short edge-loss slices
    gram_mma_kernel<<<dim3(N_NODES/128, N_NODES/128), 256, GRAM_SMEM_BYTES>>>(
        zn, ei, out);

    // scalar loss at the end of the output buffer
    if ((long long)out_size > (long long)N_NODES * N_NODES)
        write_loss_kernel<<<1, 1>>>(out);
}

// round 14
// speedup vs baseline: 1.2974x; 1.2974x over previous
#include <cuda_runtime.h>
#include <math.h>
#include <stdint.h>

#define N_NODES 12288
#define D_IN    512
#define HID     256
#define D_OUT   64
#define E_EDGES 393216

// ---------------- scratch (device globals: no runtime allocation) ----------
__device__ float  g_h0[(size_t)N_NODES * HID];
__device__ float  g_h1[(size_t)N_NODES * HID];
__device__ float  g_zn[(size_t)N_NODES * D_OUT];
__device__ double g_loss_sum;

// ---------------------------------------------------------------------------
// tf32 / cp.async / sigmoid / streaming-store helpers
// ---------------------------------------------------------------------------
__device__ __forceinline__ uint32_t f32_to_tf32(float x) {
    uint32_t r;
    asm("cvt.rna.tf32.f32 %0, %1;" : "=r"(r) : "f"(x));
    return r;
}

__device__ __forceinline__ void mma_tf32(float d[4],
                                         const uint32_t a[4],
                                         const uint32_t b[2]) {
    asm volatile(
        "mma.sync.aligned.m16n8k8.row.col.f32.tf32.tf32.f32 "
        "{%0,%1,%2,%3}, {%4,%5,%6,%7}, {%8,%9}, {%0,%1,%2,%3};"
        : "+f"(d[0]), "+f"(d[1]), "+f"(d[2]), "+f"(d[3])
        : "r"(a[0]), "r"(a[1]), "r"(a[2]), "r"(a[3]),
          "r"(b[0]), "r"(b[1]));
}

__device__ __forceinline__ void cp_async16(float* smem_dst, const float* gmem_src) {
    uint32_t s = (uint32_t)__cvta_generic_to_shared(smem_dst);
    asm volatile("cp.async.cg.shared.global [%0], [%1], 16;"
                 :: "r"(s), "l"(gmem_src));
}
#define CP_COMMIT()      asm volatile("cp.async.commit_group;")
#define CP_WAIT(n)       asm volatile("cp.async.wait_group %0;" :: "n"(n))

__device__ __forceinline__ float fast_sigmoid(float x) {
    float t;
    asm("tanh.approx.f32 %0, %1;" : "=f"(t) : "f"(x * 0.5f));
    return fmaf(t, 0.5f, 0.5f);
}

__device__ __forceinline__ void stg_cs_f2(float* p, float a, float b) {
    asm volatile("st.global.cs.v2.f32 [%0], {%1,%2};"
                 :: "l"(p), "f"(a), "f"(b) : "memory");
}
__device__ __forceinline__ void stg_cs_f1(float* p, float a) {
    asm volatile("st.global.cs.f32 [%0], %1;" :: "l"(p), "f"(a) : "memory");
}

// ---------------------------------------------------------------------------
// Encoder GEMM on tensor cores, cp.async double-buffered.
//   Layers 1,2: BM=64,  BN=128  — best measured (R12)
//   Layer  3 : BM=128, BN=64   — best measured (R11), fused row-normalize
// ---------------------------------------------------------------------------
#define LDA 36

template<int BM, int BN, bool RELU, bool NORM>
__global__ __launch_bounds__(256)
void gemm_mma_kernel(const float* __restrict__ A,
                     const float* __restrict__ W,
                     const float* __restrict__ bias,
                     float* __restrict__ C,
                     int K, int Nn)
{
    constexpr int LDW = BN + 4;
    constexpr int WN  = BN / 32;
    constexpr int WM  = 8 / WN;
    constexpr int MT  = BM / (WM * 16);
    constexpr int NT  = 4;
    static_assert(MT >= 1, "bad BM/BN combo");

    constexpr int A_FLOATS = BM * LDA;
    constexpr int W_FLOATS = 32 * LDW;
    constexpr int NEED_MAIN = 2 * (A_FLOATS + W_FLOATS);
    constexpr int NEED_STG  = NORM ? BM * 68 : 0;
    constexpr int SMEM_FLOATS = NEED_MAIN > NEED_STG ? NEED_MAIN : NEED_STG;

    __shared__ float smem[SMEM_FLOATS];
    float* Asb[2] = { smem, smem + A_FLOATS + W_FLOATS };
    float* Wsb[2] = { smem + A_FLOATS, smem + 2*A_FLOATS + W_FLOATS };

    const int tid  = threadIdx.x;
    const int lane = tid & 31;
    const int wid  = tid >> 5;
    const int wm   = (wid / WN) * (MT * 16);
    const int wn   = (wid % WN) * 32;
    const int qr   = lane >> 2;
    const int qc   = lane & 3;
    const int rowBase = blockIdx.y * BM;
    const int colBase = blockIdx.x * BN;

    auto load_tiles = [&](int kk, int buf) {
        float* As = Asb[buf];
        float* Ws = Wsb[buf];
#pragma unroll
        for (int v = tid; v < BM * 8; v += 256) {
            const int r  = v >> 3;
            const int c4 = (v & 7) * 4;
            cp_async16(&As[r * LDA + c4],
                       &A[(size_t)(rowBase + r) * K + kk + c4]);
        }
#pragma unroll
        for (int v = tid; v < 32 * (BN/4); v += 256) {
            const int kr = v / (BN/4);
            const int n4 = (v % (BN/4)) * 4;
            cp_async16(&Ws[kr * LDW + n4],
                       &W[(size_t)(kk + kr) * Nn + colBase + n4]);
        }
        CP_COMMIT();
    };

    float acc[MT][NT][4];
#pragma unroll
    for (int mt = 0; mt < MT; mt++)
#pragma unroll
        for (int nt = 0; nt < NT; nt++)
#pragma unroll
            for (int i = 0; i < 4; i++) acc[mt][nt][i] = 0.f;

    load_tiles(0, 0);

    int buf = 0;
    for (int kk = 0; kk < K; kk += 32, buf ^= 1) {
        if (kk + 32 < K) {
            load_tiles(kk + 32, buf ^ 1);
            CP_WAIT(1);
        } else {
            CP_WAIT(0);
        }
        __syncthreads();

        const float* As = Asb[buf];
        const float* Ws = Wsb[buf];
#pragma unroll
        for (int k0 = 0; k0 < 32; k0 += 8) {
            uint32_t a[MT][4], b[NT][2];
#pragma unroll
            for (int mt = 0; mt < MT; mt++) {
                const float* base = &As[(wm + mt*16 + qr) * LDA + k0 + qc];
                a[mt][0] = f32_to_tf32(base[0]);
                a[mt][1] = f32_to_tf32(base[8 * LDA]);
                a[mt][2] = f32_to_tf32(base[4]);
                a[mt][3] = f32_to_tf32(base[8 * LDA + 4]);
            }
#pragma unroll
            for (int nt = 0; nt < NT; nt++) {
                const float* base = &Ws[(k0 + qc) * LDW + wn + nt*8 + qr];
                b[nt][0] = f32_to_tf32(base[0]);
                b[nt][1] = f32_to_tf32(base[4 * LDW]);
            }
#pragma unroll
            for (int mt = 0; mt < MT; mt++)
#pragma unroll
                for (int nt = 0; nt < NT; nt++)
                    mma_tf32(acc[mt][nt], a[mt], b[nt]);
        }
        __syncthreads();
    }

    if (!NORM) {
#pragma unroll
        for (int mt = 0; mt < MT; mt++) {
#pragma unroll
            for (int nt = 0; nt < NT; nt++) {
                float* d = acc[mt][nt];
                const int c = colBase + wn + nt*8 + qc*2;
                float bx = bias[c], by = bias[c+1];
                float2 lo = make_float2(d[0] + bx, d[1] + by);
                float2 hi = make_float2(d[2] + bx, d[3] + by);
                if (RELU) {
                    lo.x = fmaxf(lo.x, 0.f); lo.y = fmaxf(lo.y, 0.f);
                    hi.x = fmaxf(hi.x, 0.f); hi.y = fmaxf(hi.y, 0.f);
                }
                const size_t r0 = rowBase + wm + mt*16 + qr;
                *reinterpret_cast<float2*>(&C[r0 * Nn + c])     = lo;
                *reinterpret_cast<float2*>(&C[(r0+8) * Nn + c]) = hi;
            }
        }
    } else {
        constexpr int LDS = 68;
        float* stg = smem;                 // BM x 64, stride 68
        __syncthreads();
#pragma unroll
        for (int mt = 0; mt < MT; mt++) {
#pragma unroll
            for (int nt = 0; nt < NT; nt++) {
                float* d = acc[mt][nt];
                const int c = wn + nt*8 + qc*2;
                float bx = bias[c], by = bias[c+1];
                const int r = wm + mt*16 + qr;
                *reinterpret_cast<float2*>(&stg[r * LDS + c]) =
                    make_float2(d[0] + bx, d[1] + by);
                *reinterpret_cast<float2*>(&stg[(r+8) * LDS + c]) =
                    make_float2(d[2] + bx, d[3] + by);
            }
        }
        __syncthreads();
#pragma unroll
        for (int rr = 0; rr < BM/8; rr++) {
            const int r = wid * (BM/8) + rr;
            float2 v = *reinterpret_cast<const float2*>(&stg[r * LDS + lane*2]);
            float ss = v.x*v.x + v.y*v.y;
#pragma unroll
            for (int o = 16; o > 0; o >>= 1)
                ss += __shfl_xor_sync(0xffffffffu, ss, o);
            float inv = rsqrtf(fmaxf(ss, 1e-30f));
            *reinterpret_cast<float2*>(&C[(size_t)(rowBase + r) * D_OUT + lane*2]) =
                make_float2(v.x * inv, v.y * inv);
        }
    }
}

// ---------------------------------------------------------------------------
// Edge reconstruction loss (edge_index is int32) — separate kernel (proven)
// ---------------------------------------------------------------------------
__global__ __launch_bounds__(256)
void edge_loss_kernel(const int* __restrict__ ei,
                      const float* __restrict__ Zn)
{
    const int lane = threadIdx.x & 31;
    const int warp = threadIdx.x >> 5;
    const int gw   = blockIdx.x * 8 + warp;
    const int nw   = gridDim.x * 8;
    float lsum = 0.f;
    for (int e = gw; e < E_EDGES; e += nw) {
        const int s = ei[e];
        const int d = ei[E_EDGES + e];
        float2 a = *reinterpret_cast<const float2*>(&Zn[(size_t)s * D_OUT + lane*2]);
        float2 b = *reinterpret_cast<const float2*>(&Zn[(size_t)d * D_OUT + lane*2]);
        float p = a.x*b.x + a.y*b.y;
#pragma unroll
        for (int o = 16; o > 0; o >>= 1) p += __shfl_xor_sync(0xffffffffu, p, o);
        if (lane == 0) lsum += log1pf(__expf(-p));
    }
    __shared__ float wsum[8];
    if (lane == 0) wsum[warp] = lsum;
    __syncthreads();
    if (threadIdx.x == 0) {
        float t = 0.f;
#pragma unroll
        for (int i = 0; i < 8; i++) t += wsum[i];
        atomicAdd(&g_loss_sum, (double)t);
    }
}

__global__ void zero_loss_kernel() { g_loss_sum = 0.0; }

__global__ void write_loss_kernel(float* __restrict__ out)
{
    out[(size_t)N_NODES * N_NODES] = (float)(g_loss_sum / (double)E_EDGES);
}

// ---------------------------------------------------------------------------
// Gram + sigmoid via tf32 mma (exact R11 measured-best structure):
//   2D grid + empty early-exit lower blocks, cp.async input staging,
//   HW-tanh sigmoid, direct-register upper-tile write + staged mirror,
//   st.global.cs output stores.
// ---------------------------------------------------------------------------
#define GRAM_LDK  68
#define GRAM_LDS  132
#define GRAM_SMEM_BYTES (2 * 128 * GRAM_LDK * 4)   // 69,632 B (>= stage 67,584)

__global__ __launch_bounds__(256)
void gram_mma_kernel(const float* __restrict__ Z, float* __restrict__ Out)
{
    extern __shared__ float smem[];
    float* As = smem;                       // raw fp32
    float* Bs = smem + 128 * GRAM_LDK;

    const int bi = blockIdx.y;
    const int bj = blockIdx.x;
    if (bj < bi) return;
    const int rowBase = bi * 128;
    const int colBase = bj * 128;

    const int tid  = threadIdx.x;
    const int lane = tid & 31;
    const int wid  = tid >> 5;
    const int wm   = (wid >> 2) * 64;
    const int wn   = (wid & 3) * 32;
    const int qr   = lane >> 2;
    const int qc   = lane & 3;

    for (int v = tid; v < 128 * 16; v += 256) {
        const int r  = v >> 4;
        const int c4 = (v & 15) * 4;
        cp_async16(&As[r * GRAM_LDK + c4],
                   &Z[(size_t)(rowBase + r) * D_OUT + c4]);
    }
    if (bj != bi) {
        for (int v = tid; v < 128 * 16; v += 256) {
            const int r  = v >> 4;
            const int c4 = (v & 15) * 4;
            cp_async16(&Bs[r * GRAM_LDK + c4],
                       &Z[(size_t)(colBase + r) * D_OUT + c4]);
        }
    }
    CP_COMMIT();
    CP_WAIT(0);
    __syncthreads();

    const float* Bp = (bj == bi) ? As : Bs;

    float acc[4][4][4];
#pragma unroll
    for (int mt = 0; mt < 4; mt++)
#pragma unroll
        for (int nt = 0; nt < 4; nt++)
#pragma unroll
            for (int i = 0; i < 4; i++) acc[mt][nt][i] = 0.f;

#pragma unroll
    for (int k0 = 0; k0 < D_OUT; k0 += 8) {
        uint32_t a[4][4], b[4][2];
#pragma unroll
        for (int mt = 0; mt < 4; mt++) {
            const float* base = &As[(wm + mt*16 + qr) * GRAM_LDK + k0 + qc];
            a[mt][0] = f32_to_tf32(base[0]);
            a[mt][1] = f32_to_tf32(base[8 * GRAM_LDK]);
            a[mt][2] = f32_to_tf32(base[4]);
            a[mt][3] = f32_to_tf32(base[8 * GRAM_LDK + 4]);
        }
#pragma unroll
        for (int nt = 0; nt < 4; nt++) {
            const float* base = &Bp[(wn + nt*8 + qr) * GRAM_LDK + k0 + qc];
            b[nt][0] = f32_to_tf32(base[0]);
            b[nt][1] = f32_to_tf32(base[4]);
        }
#pragma unroll
        for (int mt = 0; mt < 4; mt++)
#pragma unroll
            for (int nt = 0; nt < 4; nt++)
                mma_tf32(acc[mt][nt], a[mt], b[nt]);
    }

    // sigmoid (HW tanh) in registers, direct (upper) tile straight from regs
#pragma unroll
    for (int mt = 0; mt < 4; mt++) {
#pragma unroll
        for (int nt = 0; nt < 4; nt++) {
            float* d = acc[mt][nt];
            d[0] = fast_sigmoid(d[0]);
            d[1] = fast_sigmoid(d[1]);
            d[2] = fast_sigmoid(d[2]);
            d[3] = fast_sigmoid(d[3]);
            const size_t r = rowBase + wm + mt*16 + qr;
            const int    c = colBase + wn + nt*8 + qc*2;
            stg_cs_f2(&Out[r * N_NODES + c],     d[0], d[1]);
            stg_cs_f2(&Out[(r+8) * N_NODES + c], d[2], d[3]);
        }
    }

    // mirror (lower) tile: stage + transposed coalesced write
    if (bj > bi) {
        __syncthreads();
        float* stg = smem;                  // 128x128, stride 132
#pragma unroll
        for (int mt = 0; mt < 4; mt++) {
#pragma unroll
            for (int nt = 0; nt < 4; nt++) {
                float* d = acc[mt][nt];
                const int r = wm + mt*16 + qr;
                const int c = wn + nt*8 + qc*2;
                *reinterpret_cast<float2*>(&stg[r * GRAM_LDS + c]) =
                    make_float2(d[0], d[1]);
                *reinterpret_cast<float2*>(&stg[(r+8) * GRAM_LDS + c]) =
                    make_float2(d[2], d[3]);
            }
        }
        __syncthreads();
        for (int v = tid; v < 128 * 32; v += 256) {
            const int cc = v & 127;
            const int r2 = (v >> 7) * 4;
            float4 t = *reinterpret_cast<const float4*>(&stg[cc * GRAM_LDS + r2]);
            float* ob = &Out[(size_t)(colBase + r2) * N_NODES + rowBase + cc];
            stg_cs_f1(ob,             t.x);
            stg_cs_f1(ob + N_NODES,   t.y);
            stg_cs_f1(ob + 2*N_NODES, t.z);
            stg_cs_f1(ob + 3*N_NODES, t.w);
        }
    }
}

// ---------------------------------------------------------------------------
extern "C" void kernel_launch(void* const* d_in, const int* in_sizes, int n_in,
                              void* d_out, int out_size)
{
    const float* x  = (const float*)d_in[0];
    const int*   ei = (const int*)  d_in[1];
    const float* W0 = (const float*)d_in[2];
    const float* b0 = (const float*)d_in[3];
    const float* W1 = (const float*)d_in[4];
    const float* b1 = (const float*)d_in[5];
    const float* W2 = (const float*)d_in[6];
    const float* b2 = (const float*)d_in[7];
    float* out = (float*)d_out;

    void *p_h0, *p_h1, *p_zn;
    cudaGetSymbolAddress(&p_h0, g_h0);
    cudaGetSymbolAddress(&p_h1, g_h1);
    cudaGetSymbolAddress(&p_zn, g_zn);
    float* h0 = (float*)p_h0;
    float* h1 = (float*)p_h1;
    float* zn = (float*)p_zn;

    cudaFuncSetAttribute(gram_mma_kernel,
                         cudaFuncAttributeMaxDynamicSharedMemorySize,
                         GRAM_SMEM_BYTES);

    zero_loss_kernel<<<1, 1>>>();

    // encoder (tensor cores, cp.async double-buffered; per-layer best tiles)
    gemm_mma_kernel<64,  128, true,  false><<<dim3(HID/128, N_NODES/64),  256>>>(
        x,  W0, b0, h0, D_IN, HID);
    gemm_mma_kernel<64,  128, true,  false><<<dim3(HID/128, N_NODES/64),  256>>>(
        h0, W1, b1, h1, HID,  HID);
    gemm_mma_kernel<128, 64,  false, true ><<<dim3(1,       N_NODES/128), 256>>>(
        h1, W2, b2, zn, HID,  D_OUT);

    // edge loss (separate, proven config)
    edge_loss_kernel<<<1024, 256>>>(ei, zn);

    // full similarity matrix (symmetric, tensor-core, 2D grid + early exit)
    gram_mma_kernel<<<dim3(N_NODES/128, N_NODES/128), 256, GRAM_SMEM_BYTES>>>(zn, out);

    // scalar loss at the end of the output buffer
    if ((long long)out_size > (long long)N_NODES * N_NODES)
        write_loss_kernel<<<1, 1>>>(out);
}